// round 3
// baseline (speedup 1.0000x reference)
#include <cuda_runtime.h>
#include <cstdint>

typedef unsigned long long ULL;

__device__ __forceinline__ ULL pack2(float lo, float hi) {
    ULL r; asm("mov.b64 %0, {%1, %2};" : "=l"(r) : "f"(lo), "f"(hi)); return r;
}
__device__ __forceinline__ void unpack2(ULL v, float& lo, float& hi) {
    asm("mov.b64 {%0, %1}, %2;" : "=f"(lo), "=f"(hi) : "l"(v));
}
__device__ __forceinline__ ULL fma2(ULL a, ULL b, ULL c) {
    ULL d; asm("fma.rn.f32x2 %0, %1, %2, %3;" : "=l"(d) : "l"(a), "l"(b), "l"(c)); return d;
}

#define NN 256

// Hsum splat-packed: g_Hs2[node][h] = (hs, hs) as f32x2
__device__ ULL g_Hs2[4 * 256 * 64];

// ============================================================================
// K1: one block per node (b,j). Hsum[h] = sum_i relu(e[b,i,j,:]@W1 + b1)
// h-pair scheme: each fma2 lane-pair computes two different h neurons.
// ============================================================================
__global__ __launch_bounds__(128, 6)
void k_edge(const float* __restrict__ edge,
            const float* __restrict__ W1,
            const float* __restrict__ b1) {
    __shared__ float es[2][64 * 18];   // e rows duplicated (16 used) pitch 18
    __shared__ float w1s[512];
    __shared__ float hsum[64];

    const int t  = threadIdx.x;
    const int bx = blockIdx.x;
    const int j  = bx & 255;
    const int b  = bx >> 8;

    if (t < 64) hsum[t] = 0.f;
    #pragma unroll
    for (int r = 0; r < 4; r++) w1s[t + 128 * r] = W1[t + 128 * r];

    const int ii = t >> 4;     // 8 i-groups
    const int hp = t & 15;     // pairs {hp, hp+16}; halves h = pi, pi+32

    const int il = t >> 1, q = t & 1;
    const float4* src = reinterpret_cast<const float4*>(edge)
                        + ((ULL)(b * NN) * NN + j) * 2 + q;   // +512 per i

    float4 v = src[(ULL)il * 512];
    {   // stage chunk 0 (duplicated)
        float* d = &es[0][il * 18 + q * 8];
        *(float2*)&d[0] = make_float2(v.x, v.x);
        *(float2*)&d[2] = make_float2(v.y, v.y);
        *(float2*)&d[4] = make_float2(v.z, v.z);
        *(float2*)&d[6] = make_float2(v.w, v.w);
    }
    __syncthreads();   // w1s + hsum + chunk0 ready

    ULL w12[2][8], b2i[2];
    #pragma unroll
    for (int p = 0; p < 2; p++) {
        const int h0 = hp + p * 16;
        b2i[p] = pack2(b1[h0], b1[h0 + 32]);
        #pragma unroll
        for (int f = 0; f < 8; f++)
            w12[p][f] = pack2(w1s[f * 64 + h0], w1s[f * 64 + h0 + 32]);
    }

    float a0 = 0.f, a1 = 0.f, a2 = 0.f, a3 = 0.f;

    #pragma unroll 1
    for (int c = 0; c < 4; c++) {
        float4 v2;
        if (c < 3) v2 = src[(ULL)((c + 1) * 64 + il) * 512];

        const float* eb = es[c & 1];
        #pragma unroll
        for (int s = 0; s < 8; s++) {
            const float* er = &eb[(ii * 8 + s) * 18];
            ULL e[8];
            #pragma unroll
            for (int f = 0; f < 8; f++) e[f] = *(const ULL*)&er[2 * f];

            ULL h0 = fma2(e[0], w12[0][0], b2i[0]);
            ULL h1 = fma2(e[0], w12[1][0], b2i[1]);
            #pragma unroll
            for (int f = 1; f < 8; f++) {
                h0 = fma2(e[f], w12[0][f], h0);
                h1 = fma2(e[f], w12[1][f], h1);
            }
            float lo, hi;
            unpack2(h0, lo, hi);
            a0 += fmaxf(lo, 0.f); a1 += fmaxf(hi, 0.f);
            unpack2(h1, lo, hi);
            a2 += fmaxf(lo, 0.f); a3 += fmaxf(hi, 0.f);
        }

        if (c < 3) {
            float* d = &es[(c + 1) & 1][il * 18 + q * 8];
            *(float2*)&d[0] = make_float2(v2.x, v2.x);
            *(float2*)&d[2] = make_float2(v2.y, v2.y);
            *(float2*)&d[4] = make_float2(v2.z, v2.z);
            *(float2*)&d[6] = make_float2(v2.w, v2.w);
        }
        __syncthreads();   // chunk c consumed by all; next chunk staged
    }

    // reduce over ii: fold ii-pairs via shfl, then shared atomics (4-way)
    a0 += __shfl_xor_sync(0xffffffffu, a0, 16);
    a1 += __shfl_xor_sync(0xffffffffu, a1, 16);
    a2 += __shfl_xor_sync(0xffffffffu, a2, 16);
    a3 += __shfl_xor_sync(0xffffffffu, a3, 16);
    if ((t & 16) == 0) {
        atomicAdd(&hsum[hp],      a0);
        atomicAdd(&hsum[hp + 32], a1);
        atomicAdd(&hsum[hp + 16], a2);
        atomicAdd(&hsum[hp + 48], a3);
    }
    __syncthreads();
    if (t < 64) { float hv = hsum[t]; g_Hs2[bx * 64 + t] = pack2(hv, hv); }
}

// ============================================================================
// K2: 8 nodes / block, 256 threads. Full W2 (64KB) in dynamic SMEM, staged once.
// Thread = (node-quad ng, col-pair cq): per k, 1 LDS.64 (w2) reused by 4 nodes.
// ============================================================================
__global__ __launch_bounds__(256)
void k_node(const float* __restrict__ x,
            const float* __restrict__ W2,
            const float* __restrict__ b2,
            const float* __restrict__ root,
            float* __restrict__ out) {
    extern __shared__ float sm[];
    float* w2s  = sm;                         // 16384 floats (64KB)
    ULL*   hs2  = (ULL*)(sm + 16384);         // 512 ULL (4KB)
    float* wsum = sm + 16384 + 1024;          // 2048 floats (8KB)
    float* rb   = wsum + 2048;                // 256
    float* xs   = rb + 256;                   // 128

    const int t     = threadIdx.x;
    const int node0 = blockIdx.x * 8;

    // stage W2 (4096 float4, 16/thread)
    {
        const float4* wg = reinterpret_cast<const float4*>(W2);
        float4*       wd = reinterpret_cast<float4*>(w2s);
        #pragma unroll
        for (int r = 0; r < 16; r++) wd[r * 256 + t] = wg[r * 256 + t];
    }
    {
        const ULL* hg = g_Hs2 + node0 * 64;
        hs2[t]       = hg[t];
        hs2[t + 256] = hg[t + 256];
    }
    rb[t] = 256.f * b2[t] + root[t];
    if (t < 128) xs[t] = x[node0 * 16 + t];
    __syncthreads();

    const int ng = t >> 7;           // node quad: nodes 4ng..4ng+3
    const int cq = t & 127;          // col pair {2cq, 2cq+1}
    const ULL* hb = hs2 + ng * 256;  // 4 nodes x 64

    ULL acc0 = 0, acc1 = 0, acc2 = 0, acc3 = 0;
    #pragma unroll 8
    for (int k = 0; k < 64; k++) {
        ULL w = *(const ULL*)&w2s[k * 256 + 2 * cq];
        acc0 = fma2(hb[k],       w, acc0);
        acc1 = fma2(hb[64 + k],  w, acc1);
        acc2 = fma2(hb[128 + k], w, acc2);
        acc3 = fma2(hb[192 + k], w, acc3);
    }
    *(ULL*)&wsum[(ng * 4 + 0) * 256 + 2 * cq] = acc0;
    *(ULL*)&wsum[(ng * 4 + 1) * 256 + 2 * cq] = acc1;
    *(ULL*)&wsum[(ng * 4 + 2) * 256 + 2 * cq] = acc2;
    *(ULL*)&wsum[(ng * 4 + 3) * 256 + 2 * cq] = acc3;
    __syncthreads();

    if (t < 128) {
        const int n = t >> 4, d = t & 15;
        float o = 0.f;
        #pragma unroll
        for (int c = 0; c < 16; c++)
            o += xs[n * 16 + c] * (wsum[n * 256 + c * 16 + d] + rb[c * 16 + d]);
        out[(node0 + n) * 16 + d] = o;
    }
}

extern "C" void kernel_launch(void* const* d_in, const int* in_sizes, int n_in,
                              void* d_out, int out_size) {
    const float* node_attr = (const float*)d_in[0];
    const float* edge_adj  = (const float*)d_in[1];
    const float* W1        = (const float*)d_in[2];
    const float* b1        = (const float*)d_in[3];
    const float* W2        = (const float*)d_in[4];
    const float* b2        = (const float*)d_in[5];
    const float* root      = (const float*)d_in[6];
    float* out = (float*)d_out;

    static int smem_set = 0;
    if (!smem_set) {
        cudaFuncSetAttribute(k_node, cudaFuncAttributeMaxDynamicSharedMemorySize, 79360);
        smem_set = 1;
    }

    k_edge<<<1024, 128>>>(edge_adj, W1, b1);
    k_node<<<128, 256, 79360>>>(node_attr, W2, b2, root, out);
}